// round 14
// baseline (speedup 1.0000x reference)
#include <cuda_runtime.h>

#define N_REL   200
#define BATCH   16384
#define DIM     128
#define N_ENT   500000
#define TILE    8
#define NBLOCKS 296
#define THREADS 512
#define MAXT    12
#define APAD    132
#define ROWB    (DIM * 4)          // 512 bytes per entity row
#define NBUF    4

// Scratch (static __device__ globals — no allocation allowed)
__device__ int          g_cnt[N_REL];
__device__ int          g_list[N_REL * BATCH];
__device__ float        g_part[NBLOCKS];
__device__ unsigned int g_done;
__device__ unsigned int g_build_done;

// ---- tf32 warp MMA: D(16x8) += A(16x8) * B(8x8) ----
__device__ __forceinline__ void mma_tf32(float c[4],
                                         unsigned a0, unsigned a1,
                                         unsigned a2, unsigned a3,
                                         unsigned b0, unsigned b1) {
    asm volatile(
        "mma.sync.aligned.m16n8k8.row.col.f32.tf32.tf32.f32 "
        "{%0,%1,%2,%3}, {%4,%5,%6,%7}, {%8,%9}, {%0,%1,%2,%3};"
        : "+f"(c[0]), "+f"(c[1]), "+f"(c[2]), "+f"(c[3])
        : "r"(a0), "r"(a1), "r"(a2), "r"(a3), "r"(b0), "r"(b1));
}

// ---- bulk-copy + mbarrier helpers ----
__device__ __forceinline__ unsigned smem_u32(const void* p) {
    return (unsigned)__cvta_generic_to_shared(p);
}
__device__ __forceinline__ void mbar_init(unsigned mbar, unsigned count) {
    asm volatile("mbarrier.init.shared.b64 [%0], %1;" :: "r"(mbar), "r"(count) : "memory");
}
__device__ __forceinline__ void mbar_expect_tx(unsigned mbar, unsigned bytes) {
    asm volatile("mbarrier.arrive.expect_tx.shared.b64 _, [%0], %1;"
                 :: "r"(mbar), "r"(bytes) : "memory");
}
__device__ __forceinline__ void bulk_cp(unsigned dst, const void* src,
                                        unsigned bytes, unsigned mbar) {
    asm volatile(
        "cp.async.bulk.shared::cluster.global.mbarrier::complete_tx::bytes "
        "[%0], [%1], %2, [%3];"
        :: "r"(dst), "l"(src), "r"(bytes), "r"(mbar) : "memory");
}
__device__ __forceinline__ void mbar_wait(unsigned mbar, int phase) {
    asm volatile(
        "{\n\t"
        ".reg .pred P;\n\t"
        "WL_%=:\n\t"
        "mbarrier.try_wait.parity.acquire.cta.shared::cta.b64 P, [%0], %1, 0x989680;\n\t"
        "@P bra WD_%=;\n\t"
        "bra WL_%=;\n\t"
        "WD_%=:\n\t"
        "}"
        :: "r"(mbar), "r"((unsigned)phase) : "memory");
}

// Detect int64-vs-int32 index dtype from first 32 elements.
__device__ __forceinline__ int detect_is64(const void* data) {
    const unsigned int* w = (const unsigned int*)data;
    unsigned int acc = 0;
    #pragma unroll
    for (int k = 0; k < 32; k++) acc |= w[2 * k + 1];
    return (acc == 0) ? 1 : 0;
}

__device__ __forceinline__ int read_idx(const void* data, int elem, int is64, int limit) {
    long long v;
    if (is64) v = ((const long long*)data)[elem];
    else      v = ((const int*)data)[elem];
    if (v < 0) v = 0;
    if (v >= limit) v = limit - 1;
    return (int)v;
}

struct __align__(16) Buf {
    float A[16][APAD];   // rows 0-7: h[e], 8-15: ch[e]   (row-major)
    float T[16][APAD];   // rows 0-7: t[e], 8-15: ct[e]
};

// Bulk gather for one tile: 32 x 512B cp.async.bulk from warp 0.
__device__ __forceinline__ void issue_gather_bulk(
    Buf* buf, unsigned mbar, const int (*ids)[4],
    const float* __restrict__ ent, int lane)
{
    if (lane == 0) mbar_expect_tx(mbar, 32 * ROWB);
    __syncwarp();
    int e = lane & 7;
    int v = lane >> 3;                    // 0:h 1:ch 2:t 3:ct
    int id = ids[e][(v == 0) ? 0 : (v == 1) ? 2 : (v == 2) ? 1 : 3];
    float* dst = (v < 2) ? &buf->A[v * 8 + e][0] : &buf->T[(v - 2) * 8 + e][0];
    bulk_cp(smem_u32(dst), ent + (size_t)id * DIM, ROWB, mbar);
}

extern __shared__ Buf s_bufs[];           // NBUF tile buffers (dynamic smem)

// Single persistent kernel, 4-deep bulk-copy pipeline (issue-ahead = 3):
// per-tile period = max(compute, gather_latency/3) instead of gather_latency.
__global__ __launch_bounds__(THREADS, 2) void rescal_kernel(
    const void*  __restrict__ data,
    const float* __restrict__ ent,
    const float* __restrict__ rel,
    float*       __restrict__ out)
{
    __shared__ unsigned long long s_mbar[NBUF];
    __shared__ int   s_toff[N_REL];
    __shared__ int   s_ws[8], s_winc[8];
    __shared__ int   s_nt, s_is64;
    __shared__ int   st_r[MAXT], st_s[MAXT], st_n[MAXT];
    __shared__ int   s_ids[MAXT][TILE][4];
    __shared__ float wsum_all[MAXT][TILE][17];
    __shared__ float s_part[16];
    __shared__ int   s_last;

    const int tid  = threadIdx.x;
    const int lane = tid & 31;
    const int wid  = tid >> 5;
    const int g    = lane >> 2;
    const int t4   = lane & 3;

    if (tid == 0) {
        s_is64 = detect_is64(data);
        #pragma unroll
        for (int b = 0; b < NBUF; b++) mbar_init(smem_u32(&s_mbar[b]), 1);
    }
    __syncthreads();
    const int is64 = s_is64;

    // ---- phase 1: bucketing ----
    {
        int b = blockIdx.x * THREADS + tid;
        if (b < BATCH) {
            int r = read_idx(data, b * 5 + 2, is64, N_REL);
            int p = atomicAdd(&g_cnt[r], 1);
            g_list[r * BATCH + p] = b;
        }
    }
    __syncthreads();
    if (tid == 0) {
        __threadfence();
        atomicAdd(&g_build_done, 1u);
        while (*(volatile unsigned int*)&g_build_done < NBLOCKS) { }
    }
    __syncthreads();
    __threadfence();

    // ---- tile-offset scan over g_cnt ----
    int tc = 0, incl = 0;
    if (tid < 256) {
        tc = (tid < N_REL) ? (g_cnt[tid] + TILE - 1) / TILE : 0;
        int v = tc;
        #pragma unroll
        for (int o = 1; o < 32; o <<= 1) {
            int u = __shfl_up_sync(0xffffffffu, v, o);
            if (lane >= o) v += u;
        }
        if (lane == 31) s_ws[wid] = v;
        incl = v;
    }
    __syncthreads();
    if (wid == 0) {
        int x = (lane < 8) ? s_ws[lane] : 0;
        #pragma unroll
        for (int o = 1; o < 8; o <<= 1) {
            int u = __shfl_up_sync(0xffffffffu, x, o);
            if (lane >= o) x += u;
        }
        if (lane < 8) s_winc[lane] = x;
    }
    __syncthreads();
    if (tid < 256) {
        int base = (wid == 0) ? 0 : s_winc[wid - 1];
        incl += base;
        if (tid < N_REL) s_toff[tid] = incl - tc;
        if (tid == N_REL - 1) s_nt = incl;
    }
    __syncthreads();

    const int nt  = s_nt;
    const int t0  = (int)((long long)blockIdx.x * nt / NBLOCKS);
    const int t1  = (int)((long long)(blockIdx.x + 1) * nt / NBLOCKS);
    const int ntb = t1 - t0;

    // ---- per-tile metadata ----
    if (tid < ntb) {
        int t = t0 + tid;
        int lo = 0, hi = N_REL;
        while (hi - lo > 1) {
            int m = (lo + hi) >> 1;
            if (s_toff[m] <= t) lo = m; else hi = m;
        }
        int s0 = (t - s_toff[lo]) * TILE;
        int nv = g_cnt[lo] - s0;
        st_r[tid] = lo;
        st_s[tid] = s0;
        st_n[tid] = (nv > TILE) ? TILE : nv;
    }
    __syncthreads();

    // ---- prefetch entity ids ----
    if (tid < ntb * TILE) {
        int tt = tid >> 3, e = tid & 7;
        int nv = st_n[tt];
        int b  = g_list[st_r[tt] * BATCH + st_s[tt] + ((e < nv) ? e : 0)];
        s_ids[tt][e][0] = read_idx(data, b * 5 + 0, is64, N_ENT);
        s_ids[tt][e][1] = read_idx(data, b * 5 + 1, is64, N_ENT);
        s_ids[tt][e][2] = read_idx(data, b * 5 + 3, is64, N_ENT);
        s_ids[tt][e][3] = read_idx(data, b * 5 + 4, is64, N_ENT);
    }
    __syncthreads();

    float2 Breg[16];
    int    cur_r = -1;
    const int jglob = wid * 8 + g;

    // ---- pipeline prologue: fill up to NBUF-1 tiles ----
    if (wid == 0) {
        #pragma unroll
        for (int m = 0; m < NBUF - 1; m++)
            if (m < ntb)
                issue_gather_bulk(&s_bufs[m], smem_u32(&s_mbar[m]),
                                  s_ids[m], ent, lane);
    }

    for (int j = 0; j < ntb; j++) {
        mbar_wait(smem_u32(&s_mbar[j & (NBUF - 1)]), (j >> 2) & 1);
        __syncthreads();  // buf[j] visible to all; reads of buf[j-1] retired

        if (j + NBUF - 1 < ntb && wid == 0)
            issue_gather_bulk(&s_bufs[(j + NBUF - 1) & (NBUF - 1)],
                              smem_u32(&s_mbar[(j + NBUF - 1) & (NBUF - 1)]),
                              s_ids[j + NBUF - 1], ent, lane);

        const int r = st_r[j];
        if (r != cur_r) {
            const float* Rp = rel + (size_t)r * (DIM * DIM);
            #pragma unroll
            for (int kb = 0; kb < 16; kb++) {
                Breg[kb].x = __ldg(Rp + (size_t)(kb * 8 + t4) * DIM + jglob);
                Breg[kb].y = __ldg(Rp + (size_t)(kb * 8 + t4 + 4) * DIM + jglob);
            }
            cur_r = r;
        }

        const Buf* buf = &s_bufs[j & (NBUF - 1)];

        float ce[4] = {0.f, 0.f, 0.f, 0.f};
        float co[4] = {0.f, 0.f, 0.f, 0.f};
        #pragma unroll
        for (int kb = 0; kb < 16; kb += 2) {
            int k0 = kb * 8 + t4;
            unsigned e0 = __float_as_uint(buf->A[g][k0]);
            unsigned e1 = __float_as_uint(buf->A[g + 8][k0]);
            unsigned e2 = __float_as_uint(buf->A[g][k0 + 4]);
            unsigned e3 = __float_as_uint(buf->A[g + 8][k0 + 4]);
            unsigned o0 = __float_as_uint(buf->A[g][k0 + 8]);
            unsigned o1 = __float_as_uint(buf->A[g + 8][k0 + 8]);
            unsigned o2 = __float_as_uint(buf->A[g][k0 + 12]);
            unsigned o3 = __float_as_uint(buf->A[g + 8][k0 + 12]);
            mma_tf32(ce, e0, e1, e2, e3,
                     __float_as_uint(Breg[kb].x),     __float_as_uint(Breg[kb].y));
            mma_tf32(co, o0, o1, o2, o3,
                     __float_as_uint(Breg[kb + 1].x), __float_as_uint(Breg[kb + 1].y));
        }

        const int jc = wid * 8 + 2 * t4;
        float2 tp = *reinterpret_cast<const float2*>(&buf->T[g][jc]);
        float2 tn = *reinterpret_cast<const float2*>(&buf->T[g + 8][jc]);
        float contrib = (ce[0] + co[0]) * tp.x + (ce[1] + co[1]) * tp.y
                      - (ce[2] + co[2]) * tn.x - (ce[3] + co[3]) * tn.y;
        contrib += __shfl_xor_sync(0xffffffffu, contrib, 1);
        contrib += __shfl_xor_sync(0xffffffffu, contrib, 2);
        if (t4 == 0) wsum_all[j][g][wid] = contrib;
        // no barrier: wsum_all[j] only read in the batch pass below
    }

    // ---- batch combine: reduce all tiles' partials, relu, mean ----
    __syncthreads();
    float acc = 0.0f;
    for (int p = tid; p < ntb * TILE; p += THREADS) {
        int j = p >> 3, e = p & 7;
        if (e < st_n[j]) {
            float s = 0.0f;
            #pragma unroll
            for (int w = 0; w < 16; w++) s += wsum_all[j][e][w];
            s += 1.0f;                      // + MARGIN
            if (s > 0.0f) acc += s * (1.0f / BATCH);
        }
    }
    #pragma unroll
    for (int o = 16; o; o >>= 1)
        acc += __shfl_xor_sync(0xffffffffu, acc, o);
    if (lane == 0) s_part[wid] = acc;
    __syncthreads();

    if (tid == 0) {
        float total = 0.0f;
        #pragma unroll
        for (int w = 0; w < 16; w++) total += s_part[w];
        g_part[blockIdx.x] = total;
        __threadfence();
        unsigned int old = atomicAdd(&g_done, 1u);
        s_last = (old == NBLOCKS - 1) ? 1 : 0;
    }
    __syncthreads();
    if (s_last) {
        __threadfence();
        float v = (tid < NBLOCKS) ? g_part[tid] : 0.0f;
        #pragma unroll
        for (int o = 16; o; o >>= 1)
            v += __shfl_xor_sync(0xffffffffu, v, o);
        if (lane == 0) s_part[wid] = v;
        __syncthreads();
        if (wid == 0) {
            float x = (lane < 16) ? s_part[lane] : 0.0f;
            #pragma unroll
            for (int o = 8; o; o >>= 1)
                x += __shfl_xor_sync(0xffffffffu, x, o);
            if (lane == 0) out[0] = x;
        }
        if (tid < N_REL) g_cnt[tid] = 0;
        if (tid == 0) { g_done = 0u; g_build_done = 0u; }
    }
}

extern "C" void kernel_launch(void* const* d_in, const int* in_sizes, int n_in,
                              void* d_out, int out_size) {
    const void*  data = d_in[0];
    const float* ent  = (const float*)d_in[1];
    const float* rel  = (const float*)d_in[2];
    float*       out  = (float*)d_out;

    const int dyn = NBUF * (int)sizeof(Buf);   // ~67.6 KB
    cudaFuncSetAttribute(rescal_kernel,
                         cudaFuncAttributeMaxDynamicSharedMemorySize, dyn);
    rescal_kernel<<<NBLOCKS, THREADS, dyn>>>(data, ent, rel, out);
}

// round 15
// speedup vs baseline: 1.1308x; 1.1308x over previous
#include <cuda_runtime.h>

#define N_REL   200
#define BATCH   16384
#define DIM     128
#define N_ENT   500000
#define TILE    16
#define NBLOCKS 296
#define THREADS 512
#define MAXT    8
#define APAD    132
#define ROWB    (DIM * 4)
#define NBUF    2

// Scratch (static __device__ globals — no allocation allowed)
__device__ int          g_cnt[N_REL];
__device__ int          g_list[N_REL * BATCH];
__device__ float        g_part[NBLOCKS];
__device__ unsigned int g_done;
__device__ unsigned int g_build_done;

// ---- tf32 warp MMA: D(16x8) += A(16x8) * B(8x8) ----
__device__ __forceinline__ void mma_tf32(float c[4],
                                         unsigned a0, unsigned a1,
                                         unsigned a2, unsigned a3,
                                         unsigned b0, unsigned b1) {
    asm volatile(
        "mma.sync.aligned.m16n8k8.row.col.f32.tf32.tf32.f32 "
        "{%0,%1,%2,%3}, {%4,%5,%6,%7}, {%8,%9}, {%0,%1,%2,%3};"
        : "+f"(c[0]), "+f"(c[1]), "+f"(c[2]), "+f"(c[3])
        : "r"(a0), "r"(a1), "r"(a2), "r"(a3), "r"(b0), "r"(b1));
}

// ---- bulk-copy + mbarrier helpers ----
__device__ __forceinline__ unsigned smem_u32(const void* p) {
    return (unsigned)__cvta_generic_to_shared(p);
}
__device__ __forceinline__ void mbar_init(unsigned mbar, unsigned count) {
    asm volatile("mbarrier.init.shared.b64 [%0], %1;" :: "r"(mbar), "r"(count) : "memory");
}
__device__ __forceinline__ void mbar_expect_tx(unsigned mbar, unsigned bytes) {
    asm volatile("mbarrier.arrive.expect_tx.shared.b64 _, [%0], %1;"
                 :: "r"(mbar), "r"(bytes) : "memory");
}
__device__ __forceinline__ void bulk_cp(unsigned dst, const void* src,
                                        unsigned bytes, unsigned mbar) {
    asm volatile(
        "cp.async.bulk.shared::cluster.global.mbarrier::complete_tx::bytes "
        "[%0], [%1], %2, [%3];"
        :: "r"(dst), "l"(src), "r"(bytes), "r"(mbar) : "memory");
}
__device__ __forceinline__ void mbar_wait(unsigned mbar, int phase) {
    asm volatile(
        "{\n\t"
        ".reg .pred P;\n\t"
        "WL_%=:\n\t"
        "mbarrier.try_wait.parity.acquire.cta.shared::cta.b64 P, [%0], %1, 0x989680;\n\t"
        "@P bra WD_%=;\n\t"
        "bra WL_%=;\n\t"
        "WD_%=:\n\t"
        "}"
        :: "r"(mbar), "r"((unsigned)phase) : "memory");
}

// Detect int64-vs-int32 index dtype from first 32 elements.
__device__ __forceinline__ int detect_is64(const void* data) {
    const unsigned int* w = (const unsigned int*)data;
    unsigned int acc = 0;
    #pragma unroll
    for (int k = 0; k < 32; k++) acc |= w[2 * k + 1];
    return (acc == 0) ? 1 : 0;
}

__device__ __forceinline__ int read_idx(const void* data, int elem, int is64, int limit) {
    long long v;
    if (is64) v = ((const long long*)data)[elem];
    else      v = ((const int*)data)[elem];
    if (v < 0) v = 0;
    if (v >= limit) v = limit - 1;
    return (int)v;
}

struct __align__(16) Buf {
    float A[2 * TILE][APAD];   // rows 0-15: h[e], 16-31: ch[e]
    float T[2 * TILE][APAD];   // rows 0-15: t[e], 16-31: ct[e]
};

// Bulk gather for one tile: 64 x 512B cp.async.bulk, warp 0 (2 per lane).
__device__ __forceinline__ void issue_gather_bulk(
    Buf* buf, unsigned mbar, const int (*ids)[4],
    const float* __restrict__ ent, int lane)
{
    if (lane == 0) mbar_expect_tx(mbar, 64 * ROWB);
    __syncwarp();
    #pragma unroll
    for (int i = 0; i < 2; i++) {
        int r = i * 32 + lane;             // 0..63
        int e = r & 15;
        int v = r >> 4;                    // 0:h 1:ch 2:t 3:ct
        int id = ids[e][(v == 0) ? 0 : (v == 1) ? 2 : (v == 2) ? 1 : 3];
        float* dst = (v < 2) ? &buf->A[(v & 1) * TILE + e][0]
                             : &buf->T[(v & 1) * TILE + e][0];
        bulk_cp(smem_u32(dst), ent + (size_t)id * DIM, ROWB, mbar);
    }
}

extern __shared__ Buf s_bufs[];            // NBUF tile buffers (dynamic smem)

// Persistent kernel, TILE=16: half the tiles of R14 -> per-tile fixed costs
// amortized 2x; 33.8KB per gather keeps more bytes in flight per wait.
__global__ __launch_bounds__(THREADS, 2) void rescal_kernel(
    const void*  __restrict__ data,
    const float* __restrict__ ent,
    const float* __restrict__ rel,
    float*       __restrict__ out)
{
    __shared__ unsigned long long s_mbar[NBUF];
    __shared__ int   s_toff[N_REL];
    __shared__ int   s_ws[8], s_winc[8];
    __shared__ int   s_nt, s_is64;
    __shared__ int   st_r[MAXT], st_s[MAXT], st_n[MAXT];
    __shared__ int   s_ids[MAXT][TILE][4];
    __shared__ float wsum_all[MAXT][TILE][17];
    __shared__ float s_part[16];
    __shared__ int   s_last;

    const int tid  = threadIdx.x;
    const int lane = tid & 31;
    const int wid  = tid >> 5;
    const int g    = lane >> 2;
    const int t4   = lane & 3;

    if (tid == 0) {
        s_is64 = detect_is64(data);
        #pragma unroll
        for (int b = 0; b < NBUF; b++) mbar_init(smem_u32(&s_mbar[b]), 1);
    }
    __syncthreads();
    const int is64 = s_is64;

    // ---- phase 1: bucketing ----
    {
        int b = blockIdx.x * THREADS + tid;
        if (b < BATCH) {
            int r = read_idx(data, b * 5 + 2, is64, N_REL);
            int p = atomicAdd(&g_cnt[r], 1);
            g_list[r * BATCH + p] = b;
        }
    }
    __syncthreads();
    if (tid == 0) {
        __threadfence();
        atomicAdd(&g_build_done, 1u);
        while (*(volatile unsigned int*)&g_build_done < NBLOCKS) { }
    }
    __syncthreads();
    __threadfence();

    // ---- tile-offset scan over g_cnt ----
    int tc = 0, incl = 0;
    if (tid < 256) {
        tc = (tid < N_REL) ? (g_cnt[tid] + TILE - 1) / TILE : 0;
        int v = tc;
        #pragma unroll
        for (int o = 1; o < 32; o <<= 1) {
            int u = __shfl_up_sync(0xffffffffu, v, o);
            if (lane >= o) v += u;
        }
        if (lane == 31) s_ws[wid] = v;
        incl = v;
    }
    __syncthreads();
    if (wid == 0) {
        int x = (lane < 8) ? s_ws[lane] : 0;
        #pragma unroll
        for (int o = 1; o < 8; o <<= 1) {
            int u = __shfl_up_sync(0xffffffffu, x, o);
            if (lane >= o) x += u;
        }
        if (lane < 8) s_winc[lane] = x;
    }
    __syncthreads();
    if (tid < 256) {
        int base = (wid == 0) ? 0 : s_winc[wid - 1];
        incl += base;
        if (tid < N_REL) s_toff[tid] = incl - tc;
        if (tid == N_REL - 1) s_nt = incl;
    }
    __syncthreads();

    const int nt  = s_nt;
    const int t0  = (int)((long long)blockIdx.x * nt / NBLOCKS);
    const int t1  = (int)((long long)(blockIdx.x + 1) * nt / NBLOCKS);
    const int ntb = t1 - t0;

    // ---- per-tile metadata ----
    if (tid < ntb) {
        int t = t0 + tid;
        int lo = 0, hi = N_REL;
        while (hi - lo > 1) {
            int m = (lo + hi) >> 1;
            if (s_toff[m] <= t) lo = m; else hi = m;
        }
        int s0 = (t - s_toff[lo]) * TILE;
        int nv = g_cnt[lo] - s0;
        st_r[tid] = lo;
        st_s[tid] = s0;
        st_n[tid] = (nv > TILE) ? TILE : nv;
    }
    __syncthreads();

    // ---- prefetch entity ids ----
    if (tid < ntb * TILE) {
        int tt = tid >> 4, e = tid & 15;
        int nv = st_n[tt];
        int b  = g_list[st_r[tt] * BATCH + st_s[tt] + ((e < nv) ? e : 0)];
        s_ids[tt][e][0] = read_idx(data, b * 5 + 0, is64, N_ENT);
        s_ids[tt][e][1] = read_idx(data, b * 5 + 1, is64, N_ENT);
        s_ids[tt][e][2] = read_idx(data, b * 5 + 3, is64, N_ENT);
        s_ids[tt][e][3] = read_idx(data, b * 5 + 4, is64, N_ENT);
    }
    __syncthreads();

    float2 Breg[16];
    int    cur_r = -1;
    const int jglob = wid * 8 + g;

    if (ntb > 0 && wid == 0)
        issue_gather_bulk(&s_bufs[0], smem_u32(&s_mbar[0]), s_ids[0], ent, lane);

    for (int j = 0; j < ntb; j++) {
        mbar_wait(smem_u32(&s_mbar[j & 1]), (j >> 1) & 1);
        __syncthreads();  // buf[j] visible; reads of buf[(j+1)&1] retired

        if (j + 1 < ntb && wid == 0)
            issue_gather_bulk(&s_bufs[(j + 1) & 1],
                              smem_u32(&s_mbar[(j + 1) & 1]),
                              s_ids[j + 1], ent, lane);

        const int r = st_r[j];
        if (r != cur_r) {
            const float* Rp = rel + (size_t)r * (DIM * DIM);
            #pragma unroll
            for (int kb = 0; kb < 16; kb++) {
                Breg[kb].x = __ldg(Rp + (size_t)(kb * 8 + t4) * DIM + jglob);
                Breg[kb].y = __ldg(Rp + (size_t)(kb * 8 + t4 + 4) * DIM + jglob);
            }
            cur_r = r;
        }

        const Buf* buf = &s_bufs[j & 1];

        // Two m16 row-groups: h (rows 0-15) and ch (rows 16-31).
        float ch_[4] = {0.f, 0.f, 0.f, 0.f};   // pos bilinear partials
        float cc_[4] = {0.f, 0.f, 0.f, 0.f};   // neg bilinear partials
        #pragma unroll
        for (int kb = 0; kb < 16; kb++) {
            int k0 = kb * 8 + t4;
            unsigned h0 = __float_as_uint(buf->A[g][k0]);
            unsigned h1 = __float_as_uint(buf->A[g + 8][k0]);
            unsigned h2 = __float_as_uint(buf->A[g][k0 + 4]);
            unsigned h3 = __float_as_uint(buf->A[g + 8][k0 + 4]);
            unsigned q0 = __float_as_uint(buf->A[TILE + g][k0]);
            unsigned q1 = __float_as_uint(buf->A[TILE + g + 8][k0]);
            unsigned q2 = __float_as_uint(buf->A[TILE + g][k0 + 4]);
            unsigned q3 = __float_as_uint(buf->A[TILE + g + 8][k0 + 4]);
            unsigned b0 = __float_as_uint(Breg[kb].x);
            unsigned b1 = __float_as_uint(Breg[kb].y);
            mma_tf32(ch_, h0, h1, h2, h3, b0, b1);
            mma_tf32(cc_, q0, q1, q2, q3, b0, b1);
        }

        // contribs for e=g (c[0],c[1]) and e=g+8 (c[2],c[3])
        const int jc = wid * 8 + 2 * t4;
        float2 tpa = *reinterpret_cast<const float2*>(&buf->T[g][jc]);
        float2 tna = *reinterpret_cast<const float2*>(&buf->T[TILE + g][jc]);
        float2 tpb = *reinterpret_cast<const float2*>(&buf->T[g + 8][jc]);
        float2 tnb = *reinterpret_cast<const float2*>(&buf->T[TILE + g + 8][jc]);
        float ca = ch_[0] * tpa.x + ch_[1] * tpa.y - cc_[0] * tna.x - cc_[1] * tna.y;
        float cb = ch_[2] * tpb.x + ch_[3] * tpb.y - cc_[2] * tnb.x - cc_[3] * tnb.y;
        ca += __shfl_xor_sync(0xffffffffu, ca, 1);
        ca += __shfl_xor_sync(0xffffffffu, ca, 2);
        cb += __shfl_xor_sync(0xffffffffu, cb, 1);
        cb += __shfl_xor_sync(0xffffffffu, cb, 2);
        if (t4 == 0) {
            wsum_all[j][g][wid]     = ca;
            wsum_all[j][g + 8][wid] = cb;
        }
        // no barrier: wsum_all[j] only read in the batch pass below
    }

    // ---- batch combine: reduce all tiles' partials, relu, mean ----
    __syncthreads();
    float acc = 0.0f;
    for (int p = tid; p < ntb * TILE; p += THREADS) {
        int j = p >> 4, e = p & 15;
        if (e < st_n[j]) {
            float s = 0.0f;
            #pragma unroll
            for (int w = 0; w < 16; w++) s += wsum_all[j][e][w];
            s += 1.0f;                      // + MARGIN
            if (s > 0.0f) acc += s * (1.0f / BATCH);
        }
    }
    #pragma unroll
    for (int o = 16; o; o >>= 1)
        acc += __shfl_xor_sync(0xffffffffu, acc, o);
    if (lane == 0) s_part[wid] = acc;
    __syncthreads();

    if (tid == 0) {
        float total = 0.0f;
        #pragma unroll
        for (int w = 0; w < 16; w++) total += s_part[w];
        g_part[blockIdx.x] = total;
        __threadfence();
        unsigned int old = atomicAdd(&g_done, 1u);
        s_last = (old == NBLOCKS - 1) ? 1 : 0;
    }
    __syncthreads();
    if (s_last) {
        __threadfence();
        float v = (tid < NBLOCKS) ? g_part[tid] : 0.0f;
        #pragma unroll
        for (int o = 16; o; o >>= 1)
            v += __shfl_xor_sync(0xffffffffu, v, o);
        if (lane == 0) s_part[wid] = v;
        __syncthreads();
        if (wid == 0) {
            float x = (lane < 16) ? s_part[lane] : 0.0f;
            #pragma unroll
            for (int o = 8; o; o >>= 1)
                x += __shfl_xor_sync(0xffffffffu, x, o);
            if (lane == 0) out[0] = x;
        }
        if (tid < N_REL) g_cnt[tid] = 0;
        if (tid == 0) { g_done = 0u; g_build_done = 0u; }
    }
}

extern "C" void kernel_launch(void* const* d_in, const int* in_sizes, int n_in,
                              void* d_out, int out_size) {
    const void*  data = d_in[0];
    const float* ent  = (const float*)d_in[1];
    const float* rel  = (const float*)d_in[2];
    float*       out  = (float*)d_out;

    const int dyn = NBUF * (int)sizeof(Buf);   // ~67.6 KB
    cudaFuncSetAttribute(rescal_kernel,
                         cudaFuncAttributeMaxDynamicSharedMemorySize, dyn);
    rescal_kernel<<<NBLOCKS, THREADS, dyn>>>(data, ent, rel, out);
}